// round 1
// baseline (speedup 1.0000x reference)
#include <cuda_runtime.h>
#include <math.h>

// Problem dims
#define BB 64
#define NN 133          // nodes
#define NROW (BB*NN)    // 8512 rows
#define F0 75
#define F1 150
#define H1 256
#define H2 128

// ---------------- scratch (device globals; no allocation) ----------------
__device__ float g_bufA[(size_t)NROW * 256];
__device__ float g_bufB[(size_t)NROW * 256];

__device__ int   g_nz_cnt[NROW];
__device__ int   g_nz_idx[(size_t)NROW * NN];
__device__ float g_nz_val[(size_t)NROW * NN];
__device__ int   g_pl_cnt[NROW];
__device__ int   g_pl_idx[(size_t)NROW * NN];

// ---------------- build sparse lists from adj (warp per row) ----------------
__global__ void k_build_lists(const float* __restrict__ adj) {
    int warp_in_blk = threadIdx.x >> 5;
    int lane = threadIdx.x & 31;
    int wg = blockIdx.x * (blockDim.x >> 5) + warp_in_blk;
    if (wg >= NROW) return;
    const float* arow = adj + (size_t)wg * NN;

    int cnz = 0, cpl = 0;
    unsigned lt = (1u << lane) - 1u;
    for (int base = 0; base < NN; base += 32) {
        int j = base + lane;
        float a = (j < NN) ? arow[j] : 0.0f;
        bool nz = (j < NN) && (a != 0.0f);
        bool pl = (j < NN) && (a > 1e-5f);
        unsigned mnz = __ballot_sync(0xffffffffu, nz);
        unsigned mpl = __ballot_sync(0xffffffffu, pl);
        if (nz) {
            int pos = cnz + __popc(mnz & lt);
            g_nz_idx[(size_t)wg * NN + pos] = j;
            g_nz_val[(size_t)wg * NN + pos] = a;
        }
        if (pl) {
            int pos = cpl + __popc(mpl & lt);
            g_pl_idx[(size_t)wg * NN + pos] = j;
        }
        cnz += __popc(mnz);
        cpl += __popc(mpl);
    }
    if (lane == 0) { g_nz_cnt[wg] = cnz; g_pl_cnt[wg] = cpl; }
}

// ---------------- dense GEMM: C[b,i,g] = A[b,i,:] @ W[:,g] (+bias, relu) ----
// grid (19, 64); 7 rows per block (19*7 == 133). A tile in smem.
__global__ void k_dense(const float* __restrict__ A, const float* __restrict__ W,
                        const float* __restrict__ bias, float* __restrict__ C,
                        int K, int G, int do_relu) {
    int b  = blockIdx.y;
    int i0 = blockIdx.x * 7;
    extern __shared__ float sA[];               // 7*K floats
    int tot = 7 * K;
    for (int idx = threadIdx.x; idx < tot; idx += blockDim.x) {
        int r = idx / K;
        int k = idx - r * K;
        sA[idx] = A[(size_t)(b * NN + i0 + r) * K + k];
    }
    __syncthreads();

    int g = threadIdx.x;
    if (g >= G) return;

    float acc[7];
    #pragma unroll
    for (int r = 0; r < 7; r++) acc[r] = 0.0f;

    for (int k = 0; k < K; k++) {
        float w = W[(size_t)k * G + g];
        #pragma unroll
        for (int r = 0; r < 7; r++) acc[r] = fmaf(sA[r * K + k], w, acc[r]);
    }
    float bv = bias ? bias[g] : 0.0f;
    #pragma unroll
    for (int r = 0; r < 7; r++) {
        float v = acc[r] + bv;
        if (do_relu) v = fmaxf(v, 0.0f);
        C[(size_t)(b * NN + i0 + r) * G + g] = v;
    }
}

// ---------------- sparse adj matmul + bias + relu ----------------
// O[b,i,g] = relu(bias[g] + sum_e val_e * T[b, j_e, g])
__global__ void k_spmm(const float* __restrict__ T, const float* __restrict__ bias,
                       float* __restrict__ O, int G) {
    int b = blockIdx.y, i = blockIdx.x;
    int row = b * NN + i;
    __shared__ int   sj[NN];
    __shared__ float sv[NN];
    __shared__ int   scnt;
    if (threadIdx.x == 0) scnt = g_nz_cnt[row];
    __syncthreads();
    int c = scnt;
    for (int e = threadIdx.x; e < c; e += blockDim.x) {
        sj[e] = g_nz_idx[(size_t)row * NN + e];
        sv[e] = g_nz_val[(size_t)row * NN + e];
    }
    __syncthreads();
    int g = threadIdx.x;
    if (g >= G) return;
    float acc = bias[g];
    for (int e = 0; e < c; e++)
        acc = fmaf(sv[e], T[(size_t)(b * NN + sj[e]) * G + g], acc);
    O[(size_t)row * G + g] = fmaxf(acc, 0.0f);
}

// ---------------- sparse neighbor max-pool ----------------
// O[b,i,g] = cnt ? max_e H[b, j_e, g] : 0
__global__ void k_pool(const float* __restrict__ H, float* __restrict__ O, int G) {
    int b = blockIdx.y, i = blockIdx.x;
    int row = b * NN + i;
    __shared__ int sj[NN];
    __shared__ int scnt;
    if (threadIdx.x == 0) scnt = g_pl_cnt[row];
    __syncthreads();
    int c = scnt;
    for (int e = threadIdx.x; e < c; e += blockDim.x)
        sj[e] = g_pl_idx[(size_t)row * NN + e];
    __syncthreads();
    int g = threadIdx.x;
    if (g >= G) return;
    float m;
    if (c == 0) {
        m = 0.0f;
    } else {
        m = -INFINITY;
        for (int e = 0; e < c; e++)
            m = fmaxf(m, H[(size_t)(b * NN + sj[e]) * G + g]);
    }
    O[(size_t)row * G + g] = m;
}

// ---------------- fused gc4 + head (one block per batch) ----------------
__global__ void k_final(const float* __restrict__ P3,      // [B,NN,75]
                        const float* __restrict__ gc4_w,   // [75]
                        const float* __restrict__ gc4_b,   // [1]
                        const float* __restrict__ fc1_w,   // [132,3]
                        const float* __restrict__ fc1_b,   // [3]
                        const float* __restrict__ fin_w,   // [4]
                        const float* __restrict__ fin_b,   // [1]
                        float* __restrict__ out) {
    int b = blockIdx.x;
    int t = threadIdx.x;
    __shared__ float t4[NN];
    __shared__ float h[NN];
    __shared__ float rr[3];

    if (t < NN) {
        const float* p = P3 + (size_t)(b * NN + t) * F0;
        float a = 0.0f;
        #pragma unroll
        for (int k = 0; k < F0; k++) a = fmaf(p[k], gc4_w[k], a);
        t4[t] = a;
    }
    __syncthreads();

    if (t < NN) {
        int row = b * NN + t;
        int c = g_nz_cnt[row];
        float acc = gc4_b[0];
        for (int e = 0; e < c; e++)
            acc = fmaf(g_nz_val[(size_t)row * NN + e], t4[g_nz_idx[(size_t)row * NN + e]], acc);
        h[t] = fmaxf(acc, 0.0f);
    }
    __syncthreads();

    if (t < 3) {
        float a = fc1_b[t];
        for (int k = 0; k < NN - 1; k++)
            a = fmaf(h[k + 1], fc1_w[k * 3 + t], a);
        rr[t] = a;
    }
    __syncthreads();

    if (t == 0) {
        float z = h[0] * fin_w[0] + rr[0] * fin_w[1] + rr[1] * fin_w[2]
                + rr[2] * fin_w[3] + fin_b[0];
        out[b] = 1.0f / (1.0f + expf(-z));
    }
}

// ---------------- launch ----------------
extern "C" void kernel_launch(void* const* d_in, const int* in_sizes, int n_in,
                              void* d_out, int out_size) {
    const float* x     = (const float*)d_in[0];   // (64,133,75)
    const float* adj   = (const float*)d_in[1];   // (64,133,133)
    const float* emb_w = (const float*)d_in[2];   // (75,150)
    const float* emb_b = (const float*)d_in[3];
    const float* gc1_w = (const float*)d_in[4];   // (150,256)
    const float* gc1_b = (const float*)d_in[5];
    const float* gc2_w = (const float*)d_in[6];   // (256,128)
    const float* gc2_b = (const float*)d_in[7];
    const float* gc3_w = (const float*)d_in[8];   // (128,75)
    const float* gc3_b = (const float*)d_in[9];
    const float* gc4_w = (const float*)d_in[10];  // (75,1)
    const float* gc4_b = (const float*)d_in[11];
    const float* fc1_w = (const float*)d_in[12];  // (132,3)
    const float* fc1_b = (const float*)d_in[13];
    const float* fin_w = (const float*)d_in[14];  // (4,1)
    const float* fin_b = (const float*)d_in[15];
    float* out = (float*)d_out;

    float *dA, *dB;
    cudaGetSymbolAddress((void**)&dA, g_bufA);
    cudaGetSymbolAddress((void**)&dB, g_bufB);

    // 0) sparse lists from adj
    {
        int warps_per_blk = 8;
        int blocks = (NROW + warps_per_blk - 1) / warps_per_blk;
        k_build_lists<<<blocks, warps_per_blk * 32>>>(adj);
    }

    dim3 gdense(19, BB);
    dim3 gnode(NN, BB);

    // 1) emb: H1 = relu(x @ emb_w + emb_b)           -> A [.,150]
    k_dense<<<gdense, 160, 7 * F0 * sizeof(float)>>>(x, emb_w, emb_b, dA, F0, F1, 1);
    // 2) T1 = H1 @ gc1_w                              -> B [.,256]
    k_dense<<<gdense, 256, 7 * F1 * sizeof(float)>>>(dA, gc1_w, nullptr, dB, F1, H1, 0);
    // 3) Hout1 = relu(adj . T1 + gc1_b)               -> A
    k_spmm<<<gnode, 256>>>(dB, gc1_b, dA, H1);
    // 4) P1 = pool(Hout1)                             -> B
    k_pool<<<gnode, 256>>>(dA, dB, H1);
    // 5) T2 = P1 @ gc2_w                              -> A [.,128]
    k_dense<<<gdense, 128, 7 * H1 * sizeof(float)>>>(dB, gc2_w, nullptr, dA, H1, H2, 0);
    // 6) Hout2                                        -> B
    k_spmm<<<gnode, 128>>>(dA, gc2_b, dB, H2);
    // 7) P2                                           -> A
    k_pool<<<gnode, 128>>>(dB, dA, H2);
    // 8) T3 = P2 @ gc3_w                              -> B [.,75]
    k_dense<<<gdense, 128, 7 * H2 * sizeof(float)>>>(dA, gc3_w, nullptr, dB, H2, F0, 0);
    // 9) Hout3                                        -> A
    k_spmm<<<gnode, 96>>>(dB, gc3_b, dA, F0);
    // 10) P3                                          -> B
    k_pool<<<gnode, 96>>>(dA, dB, F0);
    // 11) gc4 + head                                  -> out
    k_final<<<BB, 160>>>(dB, gc4_w, gc4_b, fc1_w, fc1_b, fin_w, fin_b, out);
}